// round 4
// baseline (speedup 1.0000x reference)
#include <cuda_runtime.h>
#include <math.h>
#include <stdint.h>

#define L   256
#define DP  128
#define DB  128
#define H   8
#define DH  32
#define HD  256      // H*DH
#define LL  (L*L)    // 65536
#define LDH (L*DH)   // 8192
#define KSPLIT 8

// ---------------- scratch (device globals; no runtime alloc) ----------------
// GEMM operands stored PRE-ROUNDED to tf32 in MMA-fragment-major layouts.
__device__ __align__(128) float g_Pn[LL*DP];          // A-frag for proj
__device__ __align__(128) float g_Q [H*LL*DH];        // A-frag for qk (per head)
__device__ __align__(128) float g_K [H*LL*DH];        // B-frag for qk
__device__ __align__(128) float g_V [H*LL*DH];        // B-frag for av
__device__ __align__(128) float g_G [LL*HD];          // gate (plain fp32)
__device__ __align__(128) float g_Bp[H*LL];           // bias proj (plain)
__device__ __align__(128) float g_A [H*LL];           // attn probs, A-frag for av
__device__ __align__(128) float g_Apart[KSPLIT*H*LL]; // split-K partials (plain)
__device__ __align__(128) float g_O1[H*LL*DH];        // gated AV out, A-frag for final
__device__ __align__(128) float g_Wqt[DP*HD], g_Wkt[DP*HD], g_Wvt[DP*HD], g_Wgt[DP*HD];
__device__ __align__(128) float g_Wot[HD*DP];

__device__ __forceinline__ float fixnum(float x){
    if (isnan(x)) return 0.f;
    if (isinf(x)) return x > 0.f ? 3.4028234663852886e38f : -3.4028234663852886e38f;
    return x;
}
__device__ __forceinline__ uint32_t f2t(float x){
    uint32_t u; asm("cvt.rna.tf32.f32 %0, %1;" : "=r"(u) : "f"(x)); return u;
}
__device__ __forceinline__ float rt(float x){ return __uint_as_float(f2t(x)); }

// fragment-layout word index for a matrix consumed as MMA A-operand (m,k)
__device__ __forceinline__ size_t afrag_idx(int m, int k, int Msup){
    return ((size_t)((k>>5)*Msup + (m>>7))*32 + ((k>>3)&3)*8 + ((m>>4)&7))*128
         + ((m&7)*4 + (k&3))*4 + (((m>>3)&1) | (((k>>2)&1)<<1));
}
// fragment-layout word index for a matrix consumed as MMA B-operand (n,k)
__device__ __forceinline__ size_t bfrag_idx(int n, int k, int Nsup){
    return ((size_t)((k>>5)*Nsup + (n>>7))*16 + ((k>>3)&3)*4 + ((n>>5)&3))*256
         + ((n&7)*4 + (k&3))*8 + ((k>>2)&1)*4 + ((n>>3)&3);
}

__device__ __forceinline__ void mma_tf32(float c[4],
        uint32_t a0, uint32_t a1, uint32_t a2, uint32_t a3,
        uint32_t b0, uint32_t b1){
    asm volatile(
        "mma.sync.aligned.m16n8k8.row.col.f32.tf32.tf32.f32 "
        "{%0,%1,%2,%3},{%4,%5,%6,%7},{%8,%9},{%0,%1,%2,%3};"
        : "+f"(c[0]), "+f"(c[1]), "+f"(c[2]), "+f"(c[3])
        : "r"(a0), "r"(a1), "r"(a2), "r"(a3), "r"(b0), "r"(b1));
}
__device__ __forceinline__ void cpa16(uint32_t s_dst, const void* g_src){
    asm volatile("cp.async.cg.shared.global [%0], [%1], 16;" :: "r"(s_dst), "l"(g_src));
}
#define CP_COMMIT asm volatile("cp.async.commit_group;")
#define CP_WAIT1  asm volatile("cp.async.wait_group 1;")

__device__ __forceinline__ uint4 ld128s(uint32_t a){
    uint4 v;
    asm volatile("ld.shared.v4.b32 {%0,%1,%2,%3}, [%4];"
        : "=r"(v.x), "=r"(v.y), "=r"(v.z), "=r"(v.w) : "r"(a));
    return v;
}

// ---------------- generic 128x128 GEMM core over fragment layouts -----------
// Stage = 128m x 32k A (16KB dense) + 128n x 32k B (16KB, smem XOR-swizzled).
// 3-stage cp.async pipeline, 8 warps, warp tile 64x32.
__device__ __forceinline__ void gemm_core(
        const float* __restrict__ Ap, size_t Astep,
        const float* __restrict__ Bp, size_t Bstep,
        int NS, float c[4][4][4])
{
    extern __shared__ char smem[];
    const int tid = threadIdx.x;
    const int warp = tid >> 5, lane = tid & 31;
    const int warpn = warp & 3;
    const int wmt = (warp >> 2) * 4;
    const uint32_t sbase = (uint32_t)__cvta_generic_to_shared(smem);
    const uint32_t sw = (lane >> 2) & 1;

    auto load_stage = [&](int s, int slot){
        const float* A = Ap + (size_t)s * Astep;
        const float* B = Bp + (size_t)s * Bstep;
        uint32_t dA = sbase + slot * 32768u;
        uint32_t dB = dA + 16384u;
        #pragma unroll
        for (int it = 0; it < 4; it++){
            int ca = tid + it*256;
            cpa16(dA + ca*16, A + (size_t)ca*4);
            int cs = ca ^ ((ca >> 3) & 1);
            cpa16(dB + cs*16, B + (size_t)ca*4);
        }
    };
    load_stage(0,0); CP_COMMIT;
    load_stage(1,1); CP_COMMIT;
    for (int s = 0; s < NS; s++){
        CP_WAIT1; __syncthreads();
        if (s + 2 < NS) load_stage(s+2, (s+2)%3);
        CP_COMMIT;
        uint32_t aS = sbase + (uint32_t)(s%3)*32768u;
        uint32_t bS = aS + 16384u;
        #pragma unroll
        for (int ktl = 0; ktl < 4; ktl++){
            uint32_t btile = bS + (ktl*4 + warpn)*1024u;
            uint4 b0 = ld128s(btile + lane*32 + sw*16);
            uint4 b1 = ld128s(btile + lane*32 + (sw^1)*16);
            uint4 a[4];
            #pragma unroll
            for (int mt = 0; mt < 4; mt++)
                a[mt] = ld128s(aS + ((ktl*8 + wmt + mt) << 9) + lane*16);
            #pragma unroll
            for (int mt = 0; mt < 4; mt++){
                mma_tf32(c[mt][0], a[mt].x,a[mt].y,a[mt].z,a[mt].w, b0.x, b1.x);
                mma_tf32(c[mt][1], a[mt].x,a[mt].y,a[mt].z,a[mt].w, b0.y, b1.y);
                mma_tf32(c[mt][2], a[mt].x,a[mt].y,a[mt].z,a[mt].w, b0.z, b1.z);
                mma_tf32(c[mt][3], a[mt].x,a[mt].y,a[mt].z,a[mt].w, b0.w, b1.w);
            }
        }
    }
}

#define SMEM_G (3*32768)

// -------- kernel 0: convert weights to tf32 fragment layouts ----------------
__global__ void cvt_weights(const float* __restrict__ Wq, const float* __restrict__ Wk,
                            const float* __restrict__ Wv, const float* __restrict__ Wg,
                            const float* __restrict__ Wo){
    int i = blockIdx.x*256 + threadIdx.x;   // 32768
    int d = i >> 8, mm = i & 255;
    size_t w = bfrag_idx(mm, d, 2);
    g_Wqt[w] = rt(Wq[i]); g_Wkt[w] = rt(Wk[i]);
    g_Wvt[w] = rt(Wv[i]); g_Wgt[w] = rt(Wg[i]);
    int kd = i >> 7, n = i & 127;
    g_Wot[bfrag_idx(n, kd, 1)] = rt(Wo[i]);
}

// -------- kernel 1: nan_to_num + transpose + LN(pair) -> A-frag -------------
__global__ void ln_pair_kernel(const float* __restrict__ pair,
                               const float* __restrict__ g,
                               const float* __restrict__ b){
    int m = blockIdx.x*8 + (threadIdx.x >> 5);   // global row = a*L + b2
    int lane = threadIdx.x & 31;
    int a = m >> 8, b2 = m & 255;
    float4 x = *(const float4*)&pair[((size_t)b2*L + a)*DP + lane*4];
    x.x = fixnum(x.x); x.y = fixnum(x.y); x.z = fixnum(x.z); x.w = fixnum(x.w);
    float s = x.x + x.y + x.z + x.w;
    #pragma unroll
    for (int o = 16; o > 0; o >>= 1) s += __shfl_xor_sync(0xffffffffu, s, o);
    float mean = s * (1.f/DP);
    float c0 = x.x-mean, c1 = x.y-mean, c2 = x.z-mean, c3 = x.w-mean;
    float q = c0*c0 + c1*c1 + c2*c2 + c3*c3;
    #pragma unroll
    for (int o = 16; o > 0; o >>= 1) q += __shfl_xor_sync(0xffffffffu, q, o);
    float rs = rsqrtf(q * (1.f/DP) + 1e-5f);
    float4 gv = *(const float4*)&g[lane*4];
    float4 bv = *(const float4*)&b[lane*4];
    int k = lane*4;
    g_Pn[afrag_idx(m, k+0, 512)] = rt(c0*rs*gv.x + bv.x);
    g_Pn[afrag_idx(m, k+1, 512)] = rt(c1*rs*gv.y + bv.y);
    g_Pn[afrag_idx(m, k+2, 512)] = rt(c2*rs*gv.z + bv.z);
    g_Pn[afrag_idx(m, k+3, 512)] = rt(c3*rs*gv.w + bv.w);
}

// -------- kernel 2: bias LN + projection to per-head bias (plain) -----------
__global__ void bias_proj_kernel(const float* __restrict__ bias,
                                 const float* __restrict__ g,
                                 const float* __restrict__ bb,
                                 const float* __restrict__ Wb){
    int bid = blockIdx.x;           // i*L + j
    int i = bid >> 8, j = bid & 255;
    int e = threadIdx.x;            // 128
    float x = fixnum(bias[(j*L + i)*DB + e]);
    __shared__ float ws[4];
    __shared__ float xn[128];
    __shared__ float red[128];
    float s = x;
    #pragma unroll
    for (int o = 16; o > 0; o >>= 1) s += __shfl_xor_sync(0xffffffffu, s, o);
    if ((e & 31) == 0) ws[e >> 5] = s;
    __syncthreads();
    float m = (ws[0]+ws[1]+ws[2]+ws[3]) * (1.f/DB);
    float c = x - m;
    float q = c*c;
    #pragma unroll
    for (int o = 16; o > 0; o >>= 1) q += __shfl_xor_sync(0xffffffffu, q, o);
    __syncthreads();
    if ((e & 31) == 0) ws[e >> 5] = q;
    __syncthreads();
    float v = (ws[0]+ws[1]+ws[2]+ws[3]) * (1.f/DB);
    xn[e] = c * rsqrtf(v + 1e-5f) * g[e] + bb[e];
    __syncthreads();
    int h = e & 7;
    int es = e >> 3;
    float acc = 0.f;
    #pragma unroll
    for (int ss = 0; ss < 8; ss++){
        int ee = es + ss*16;
        acc += xn[ee] * Wb[ee*H + h];
    }
    red[e] = acc; __syncthreads();
    if (e < 8){
        float t = 0.f;
        #pragma unroll
        for (int ss = 0; ss < 16; ss++) t += red[e + ss*8];
        g_Bp[(e*L + i)*L + j] = t;
    }
}

// -------- kernel 3: projection GEMM ------------------------------------------
__global__ __launch_bounds__(256) void proj_mma(const float* __restrict__ bg){
    int n0 = blockIdx.x * 128;
    int r0 = blockIdx.y * 128;
    int which = n0 >> 8, nsup = (n0 >> 7) & 1, nn0 = n0 & 255;
    const float* W = (which==0)?g_Wqt:(which==1)?g_Wkt:(which==2)?g_Wvt:g_Wgt;
    float c[4][4][4] = {};
    gemm_core(g_Pn + (size_t)(r0>>7)*4096, (size_t)512*4096,
              W + (size_t)nsup*4096, (size_t)2*4096, 4, c);

    int tid = threadIdx.x, warp = tid>>5, lane = tid&31;
    int gid = lane>>2, tig = lane&3;
    int wm = (warp>>2)*64, wn = (warp&3)*32;
    const float SQ = 0.17677669529663687f;  // 1/sqrt(DH)
    const float SK = 0.0625f;               // 1/sqrt(L)
    #pragma unroll
    for (int mt = 0; mt < 4; mt++){
        #pragma unroll
        for (int nt = 0; nt < 4; nt++){
            #pragma unroll
            for (int half = 0; half < 2; half++){
                int row = r0 + wm + mt*16 + gid + half*8;
                int a_ = row >> 8, b2 = row & 255;
                int mm = nn0 + wn + nt*8 + 2*tig;
                float y0 = c[mt][nt][half*2+0];
                float y1 = c[mt][nt][half*2+1];
                if (which == 3){
                    y0 = 1.f/(1.f + expf(-(y0 + bg[mm])));
                    y1 = 1.f/(1.f + expf(-(y1 + bg[mm+1])));
                    *(float2*)&g_G[(size_t)row*HD + mm] = make_float2(y0, y1);
                } else {
                    int hh = mm >> 5, cc = mm & 31;
                    int kq = a_*32 + cc;
                    size_t hb = (size_t)hh * 2097152;
                    if (which == 0){
                        g_Q[hb + afrag_idx(b2, kq,   2)] = rt(y0*SQ);
                        g_Q[hb + afrag_idx(b2, kq+1, 2)] = rt(y1*SQ);
                    } else if (which == 1){
                        g_K[hb + bfrag_idx(b2, kq,   2)] = rt(y0*SK);
                        g_K[hb + bfrag_idx(b2, kq+1, 2)] = rt(y1*SK);
                    } else {
                        g_V[hb + bfrag_idx(kq,   b2, 64)] = rt(y0);
                        g_V[hb + bfrag_idx(kq+1, b2, 64)] = rt(y1);
                    }
                }
            }
        }
    }
}

// -------- kernel 4: QK^T logits, split-K (plain output) ---------------------
__global__ __launch_bounds__(256) void qk_mma(){
    int ks_id = blockIdx.x;
    int tile  = blockIdx.y;
    int i0 = (tile >> 1) * 128, j0 = (tile & 1) * 128;
    int h = blockIdx.z;
    size_t hb = (size_t)h * 2097152;
    float c[4][4][4] = {};
    gemm_core(g_Q + hb + ((size_t)(ks_id*32)*2 + (i0>>7))*4096, 8192,
              g_K + hb + ((size_t)(ks_id*32)*2 + (j0>>7))*4096, 8192, 32, c);

    int tid = threadIdx.x, warp = tid>>5, lane = tid&31;
    int gid = lane>>2, tig = lane&3;
    int wm = (warp>>2)*64, wn = (warp&3)*32;
    float* dst = g_Apart + ((size_t)ks_id*H + h) * LL;
    #pragma unroll
    for (int mt = 0; mt < 4; mt++)
        #pragma unroll
        for (int nt = 0; nt < 4; nt++)
            #pragma unroll
            for (int half = 0; half < 2; half++){
                int i = i0 + wm + mt*16 + gid + half*8;
                int j = j0 + wn + nt*8 + 2*tig;
                *(float2*)&dst[(size_t)i*L + j] =
                    make_float2(c[mt][nt][half*2], c[mt][nt][half*2+1]);
            }
}

// -------- kernel 5: reduce split-K + bias + mask + softmax -> A-frag --------
__global__ void softmax_fused(const int* __restrict__ mask){
    int row = blockIdx.x;      // h*L + i
    int h = row >> 8, i = row & 255;
    int j = threadIdx.x;       // 256
    float v = 0.f;
    #pragma unroll
    for (int s = 0; s < KSPLIT; s++)
        v += g_Apart[(((size_t)s*H + h)*L + i)*L + j];
    v += g_Bp[(size_t)row*L + j];
    if (mask[i] == 0 || mask[j] == 0) v = -1e9f;
    __shared__ float red[256];
    red[j] = v; __syncthreads();
    for (int s = 128; s > 0; s >>= 1){ if (j < s) red[j] = fmaxf(red[j], red[j+s]); __syncthreads(); }
    float mx = red[0];
    __syncthreads();
    float e = expf(v - mx);
    red[j] = e; __syncthreads();
    for (int s = 128; s > 0; s >>= 1){ if (j < s) red[j] += red[j+s]; __syncthreads(); }
    g_A[(size_t)h*65536 + afrag_idx(i, j, 2)] = rt(e / red[0]);
}

// -------- kernel 6: AV GEMM, gate fused, output -> A-frag for final ---------
__global__ __launch_bounds__(256) void av_mma(){
    int n0 = blockIdx.x * 128;
    int i0 = blockIdx.y * 128;
    int h  = blockIdx.z;
    float c[4][4][4] = {};
    gemm_core(g_A + (size_t)h*65536 + (size_t)(i0>>7)*4096, 8192,
              g_V + (size_t)h*2097152 + (size_t)(n0>>7)*4096, (size_t)64*4096, 8, c);

    int tid = threadIdx.x, warp = tid>>5, lane = tid&31;
    int gid = lane>>2, tig = lane&3;
    int wm = (warp>>2)*64, wn = (warp&3)*32;
    #pragma unroll
    for (int mt = 0; mt < 4; mt++)
        #pragma unroll
        for (int nt = 0; nt < 4; nt++)
            #pragma unroll
            for (int half = 0; half < 2; half++){
                int i = i0 + wm + mt*16 + gid + half*8;
                int n = n0 + wn + nt*8 + 2*tig;
                int kk = n >> 5, d = n & 31;
                float2 gg = *(const float2*)&g_G[((size_t)i*L + kk)*HD + h*DH + d];
                int mrow = i*256 + kk;
                g_O1[afrag_idx(mrow, h*32 + d,     512)] = rt(c[mt][nt][half*2]   * gg.x);
                g_O1[afrag_idx(mrow, h*32 + d + 1, 512)] = rt(c[mt][nt][half*2+1] * gg.y);
            }
}

// -------- kernel 7: (gated out) @ Wo + bo, transpose + mask ------------------
__global__ __launch_bounds__(256) void final_mma(
        const int* __restrict__ mask, const float* __restrict__ bo,
        float* __restrict__ out){
    int r0 = blockIdx.x * 128;           // rows r = i*256 + k
    int i  = r0 >> 8;
    int k0r = r0 & 255;
    float c[4][4][4] = {};
    gemm_core(g_O1 + (size_t)(r0>>7)*4096, (size_t)512*4096,
              g_Wot, 4096, 8, c);

    int tid = threadIdx.x, warp = tid>>5, lane = tid&31;
    int gid = lane>>2, tig = lane&3;
    int wm = (warp>>2)*64, wn = (warp&3)*32;
    bool mi = (mask[i] == 0);
    #pragma unroll
    for (int mt = 0; mt < 4; mt++)
        #pragma unroll
        for (int nt = 0; nt < 4; nt++)
            #pragma unroll
            for (int half = 0; half < 2; half++){
                int rowl = wm + mt*16 + gid + half*8;
                int k = k0r + rowl;
                int col = wn + nt*8 + 2*tig;
                float y0 = c[mt][nt][half*2+0] + bo[col];
                float y1 = c[mt][nt][half*2+1] + bo[col+1];
                if (mi || mask[k] == 0){ y0 = 0.f; y1 = 0.f; }
                *(float2*)&out[((size_t)k*L + i)*DP + col] = make_float2(y0, y1);
            }
}

// ---------------------------------------------------------------------------
extern "C" void kernel_launch(void* const* d_in, const int* in_sizes, int n_in,
                              void* d_out, int out_size){
    const float* pair   = (const float*)d_in[0];
    const float* bias   = (const float*)d_in[1];
    const int*   mask   = (const int*)  d_in[2];
    const float* g_pair = (const float*)d_in[3];
    const float* b_pair = (const float*)d_in[4];
    const float* g_bias = (const float*)d_in[5];
    const float* b_bias = (const float*)d_in[6];
    const float* Wq     = (const float*)d_in[7];
    const float* Wk     = (const float*)d_in[8];
    const float* Wv     = (const float*)d_in[9];
    const float* Wb     = (const float*)d_in[10];
    const float* Wg     = (const float*)d_in[11];
    const float* bg     = (const float*)d_in[12];
    const float* Wo     = (const float*)d_in[13];
    const float* bo     = (const float*)d_in[14];
    float* out = (float*)d_out;

    static int inited = 0;
    if (!inited){
        cudaFuncSetAttribute(proj_mma,  cudaFuncAttributeMaxDynamicSharedMemorySize, SMEM_G);
        cudaFuncSetAttribute(qk_mma,    cudaFuncAttributeMaxDynamicSharedMemorySize, SMEM_G);
        cudaFuncSetAttribute(av_mma,    cudaFuncAttributeMaxDynamicSharedMemorySize, SMEM_G);
        cudaFuncSetAttribute(final_mma, cudaFuncAttributeMaxDynamicSharedMemorySize, SMEM_G);
        inited = 1;
    }

    cvt_weights     <<<128, 256>>>(Wq, Wk, Wv, Wg, Wo);
    ln_pair_kernel  <<<LL/8, 256>>>(pair, g_pair, b_pair);
    bias_proj_kernel<<<LL, 128>>>(bias, g_bias, b_bias, Wb);
    proj_mma        <<<dim3(8, 512), 256, SMEM_G>>>(bg);
    qk_mma          <<<dim3(KSPLIT, 4, H), 256, SMEM_G>>>();
    softmax_fused   <<<H*L, 256>>>(mask);
    av_mma          <<<dim3(64, 2, H), 256, SMEM_G>>>();
    final_mma       <<<512, 256, SMEM_G>>>(mask, bo, out);
}